// round 1
// baseline (speedup 1.0000x reference)
#include <cuda_runtime.h>

// Multi-scale SSIM quadtree loss, N=256, 9 levels (d=8..0).
// Level d: blocks of side h = 256>>d, mu = block_sum / h (faithful reference bug),
// weight W[d] = K_LOSS[d] * 0.25^d, K_LOSS = {9,8,7,6,5,4,3,2,1}.
//
// Single kernel: 256 CTAs x 256 threads. Each CTA owns a 16x16 tile and does
// levels d=8..4; last-CTA (atomic ticket) finishes d=3..0 + final reduction.

#define SSIM_C1 0.2f

__device__ float g_Sx[256];
__device__ float g_Sy[256];
__device__ float g_partial[256];
__device__ unsigned int g_count = 0;

// W[d] = K_LOSS[d] / 4^d
__constant__ float c_W[9] = {
    9.0f,                 // d=0: 9
    2.0f,                 // d=1: 8/4
    0.4375f,              // d=2: 7/16
    0.09375f,             // d=3: 6/64
    0.01953125f,          // d=4: 5/256
    0.00390625f,          // d=5: 4/1024
    0.000732421875f,      // d=6: 3/4096
    0.0001220703125f,     // d=7: 2/16384
    0.0000152587890625f   // d=8: 1/65536
};

__device__ __forceinline__ float loss_term(float sx, float sy, float invh) {
    float mx = sx * invh;
    float my = sy * invh;
    float ssim = (2.0f * mx * my + SSIM_C1) / (mx * mx + my * my + SSIM_C1);
    return 1.0f - ssim;
}

__global__ void __launch_bounds__(256) Loss_13967233646850_kernel(
    const float* __restrict__ x, const float* __restrict__ y,
    float* __restrict__ out)
{
    __shared__ float Ax[256], Ay[256];   // ping buffer (up to 16x16)
    __shared__ float Bx[64],  By[64];    // pong buffer (up to 8x8)
    __shared__ float red[256];
    __shared__ bool  isLast;

    const int tid = threadIdx.x;
    const int b   = blockIdx.x;

    // ---- Phase A: per-tile levels d=8..4 ----
    const int lx = tid & 15, ly = tid >> 4;
    const int gx = (b & 15) * 16 + lx;
    const int gy = (b >> 4) * 16 + ly;
    const int idx = gy * 256 + gx;

    const float px = x[idx];
    const float py = y[idx];

    float acc = c_W[8] * loss_term(px, py, 1.0f);   // d=8, h=1

    Ax[tid] = px; Ay[tid] = py;
    __syncthreads();

    float *cx = Ax, *cy = Ay, *nx = Bx, *ny = By;
    int n = 16, d = 8;
    while (n > 1) {
        const int m = n >> 1;
        --d;                              // d = 7,6,5,4 ; h = 16/m
        if (tid < m * m) {
            const int r = tid / m, c = tid % m;
            const float* rx0 = cx + (2 * r) * n + 2 * c;
            const float* ry0 = cy + (2 * r) * n + 2 * c;
            const float sx2 = rx0[0] + rx0[1] + rx0[n] + rx0[n + 1];
            const float sy2 = ry0[0] + ry0[1] + ry0[n] + ry0[n + 1];
            nx[tid] = sx2; ny[tid] = sy2;
            const float invh = (float)m * (1.0f / 16.0f);
            acc += c_W[d] * loss_term(sx2, sy2, invh);
        }
        __syncthreads();
        float* t;
        t = cx; cx = nx; nx = t;
        t = cy; cy = ny; ny = t;
        n = m;
    }
    // tile sums now in cx[0], cy[0]

    red[tid] = acc;
    __syncthreads();
    #pragma unroll
    for (int s = 128; s > 0; s >>= 1) {
        if (tid < s) red[tid] += red[tid + s];
        __syncthreads();
    }

    if (tid == 0) {
        g_partial[b] = red[0];
        g_Sx[b]      = cx[0];
        g_Sy[b]      = cy[0];
        __threadfence();
        unsigned int ticket = atomicAdd(&g_count, 1u);
        isLast = (ticket == gridDim.x - 1);
    }
    __syncthreads();
    if (!isLast) return;

    // ---- Phase B: last CTA finishes d=3..0 + global reduce ----
    __threadfence();
    const float sxv = g_Sx[tid];
    const float syv = g_Sy[tid];
    float acc2 = g_partial[tid];
    __syncthreads();                       // reuse shared buffers safely
    Ax[tid] = sxv; Ay[tid] = syv;
    __syncthreads();

    cx = Ax; cy = Ay; nx = Bx; ny = By;
    n = 16; d = 4;
    while (n > 1) {
        const int m = n >> 1;
        --d;                               // d = 3,2,1,0 ; h = 256/m
        if (tid < m * m) {
            const int r = tid / m, c = tid % m;
            const float* rx0 = cx + (2 * r) * n + 2 * c;
            const float* ry0 = cy + (2 * r) * n + 2 * c;
            const float sx2 = rx0[0] + rx0[1] + rx0[n] + rx0[n + 1];
            const float sy2 = ry0[0] + ry0[1] + ry0[n] + ry0[n + 1];
            nx[tid] = sx2; ny[tid] = sy2;
            const float invh = (float)m * (1.0f / 256.0f);
            acc2 += c_W[d] * loss_term(sx2, sy2, invh);
        }
        __syncthreads();
        float* t;
        t = cx; cx = nx; nx = t;
        t = cy; cy = ny; ny = t;
        n = m;
    }

    red[tid] = acc2;
    __syncthreads();
    #pragma unroll
    for (int s = 128; s > 0; s >>= 1) {
        if (tid < s) red[tid] += red[tid + s];
        __syncthreads();
    }

    if (tid == 0) {
        out[0] = red[0];
        g_count = 0;   // reset for next graph replay
    }
}

extern "C" void kernel_launch(void* const* d_in, const int* in_sizes, int n_in,
                              void* d_out, int out_size) {
    const float* x = (const float*)d_in[0];
    const float* y = (const float*)d_in[1];
    float* out = (float*)d_out;
    Loss_13967233646850_kernel<<<256, 256>>>(x, y, out);
}

// round 2
// speedup vs baseline: 1.0188x; 1.0188x over previous
#include <cuda_runtime.h>

// Multi-scale SSIM quadtree loss, N=256, 9 levels (d=8..0).
// Level d: blocks of side h=256>>d, mu = block_sum/h (faithful reference bug),
// weight W[d] = K_LOSS[d]*0.25^d, K_LOSS={9,8,7,6,5,4,3,2,1}.
//
// Warp-shuffle quadtree: each warp owns an 8x8 block, lane l -> (row=l>>2,
// colpair=l&3), 2 pixels/lane via float2. shfl_xor masks {4},{8,1},{16,2}
// build 2x2/4x4/8x8 sums replicated across lanes; each lane adds the term
// with weight / replication (exact pow2). 256 CTAs x 128 thr (4 warps = one
// 16x16 tile); last-CTA ticket finishes the 16x16 tile grid (d=3..0) with
// the same shuffle structure. 3 barriers total (was ~26).

#define SSIM_C1 0.2f

__device__ float g_Sx[256];
__device__ float g_Sy[256];
__device__ float g_partial[256];
__device__ unsigned int g_count = 0;

// Weights pre-divided by lane replication factor (all exact in fp32):
#define W8_R   1.52587890625e-05f   // 1/65536            (d=8, rep 1)
#define W7_R   6.103515625e-05f     // (2/16384)/2        (d=7, rep 2)
#define W6_R   9.1552734375e-05f    // (3/4096)/8         (d=6, rep 8)
#define W5_R   1.220703125e-04f     // (4/1024)/32        (d=5, rep 32)
#define W4_F   0.01953125f          // 5/256              (d=4, once)
#define W3_R   0.046875f            // (6/64)/2           (d=3, rep 2)
#define W2_R   0.0546875f           // (7/16)/8           (d=2, rep 8)
#define W1_R   0.0625f              // (8/4)/32           (d=1, rep 32)
#define W0_F   9.0f                 // 9                  (d=0, once)

__device__ __forceinline__ float loss_term(float sx, float sy, float invh) {
    float mx = sx * invh;
    float my = sy * invh;
    return 1.0f - (2.0f * mx * my + SSIM_C1) / (mx * mx + my * my + SSIM_C1);
}

// Quadtree over an 8x8 grid of per-lane (1x2) sums. Adds the three interior
// level terms to acc and returns the full 8x8 sums via s8x/s8y.
// w3/w2/w1 are the (replication-divided) weights; ih2/ih4/ih8 the 1/h values.
__device__ __forceinline__ void warp_quadtree(
    float s1x, float s1y, float& acc, float& s8x, float& s8y,
    float w2x2, float ih2, float w4x4, float ih4, float w8x8, float ih8)
{
    // 2x2 (vertical pair of 1x2): lanes l, l^4 share it
    float s2x = s1x + __shfl_xor_sync(0xffffffffu, s1x, 4);
    float s2y = s1y + __shfl_xor_sync(0xffffffffu, s1y, 4);
    acc += w2x2 * loss_term(s2x, s2y, ih2);
    // 4x4: rows +-2 (mask 8), colpairs +-1 (mask 1)
    float s4x = s2x + __shfl_xor_sync(0xffffffffu, s2x, 8);
    float s4y = s2y + __shfl_xor_sync(0xffffffffu, s2y, 8);
    s4x += __shfl_xor_sync(0xffffffffu, s4x, 1);
    s4y += __shfl_xor_sync(0xffffffffu, s4y, 1);
    acc += w4x4 * loss_term(s4x, s4y, ih4);
    // 8x8: rows +-4 (mask 16), colpairs +-2 (mask 2)
    s8x = s4x + __shfl_xor_sync(0xffffffffu, s4x, 16);
    s8y = s4y + __shfl_xor_sync(0xffffffffu, s4y, 16);
    s8x += __shfl_xor_sync(0xffffffffu, s8x, 2);
    s8y += __shfl_xor_sync(0xffffffffu, s8y, 2);
    acc += w8x8 * loss_term(s8x, s8y, ih8);
}

__device__ __forceinline__ float warp_sum(float v) {
    v += __shfl_xor_sync(0xffffffffu, v, 16);
    v += __shfl_xor_sync(0xffffffffu, v, 8);
    v += __shfl_xor_sync(0xffffffffu, v, 4);
    v += __shfl_xor_sync(0xffffffffu, v, 2);
    v += __shfl_xor_sync(0xffffffffu, v, 1);
    return v;
}

__global__ void __launch_bounds__(128) Loss_13967233646850_kernel(
    const float* __restrict__ x, const float* __restrict__ y,
    float* __restrict__ out)
{
    __shared__ float sSx[4], sSy[4], sAcc[4];
    __shared__ bool  isLast;

    const int tid  = threadIdx.x;
    const int lane = tid & 31;
    const int w    = tid >> 5;           // warp 0..3 -> quadrant of 16x16 tile
    const int b    = blockIdx.x;

    // ---- Phase A: tile levels d=8..4 ----
    {
        const int row = (b >> 4) * 16 + (w >> 1) * 8 + (lane >> 2);
        const int col = (b & 15) * 16 + (w & 1) * 8 + (lane & 3) * 2;
        const int idx = row * 256 + col;

        const float2 px = *(const float2*)(x + idx);
        const float2 py = *(const float2*)(y + idx);

        float acc = W8_R * (loss_term(px.x, py.x, 1.0f) +
                            loss_term(px.y, py.y, 1.0f));
        float s8x, s8y;
        warp_quadtree(px.x + px.y, py.x + py.y, acc, s8x, s8y,
                      W7_R, 0.5f, W6_R, 0.25f, W5_R, 0.125f);
        acc = warp_sum(acc);
        if (lane == 0) { sSx[w] = s8x; sSy[w] = s8y; sAcc[w] = acc; }
    }
    __syncthreads();

    if (tid == 0) {
        float Sx = sSx[0] + sSx[1] + sSx[2] + sSx[3];
        float Sy = sSy[0] + sSy[1] + sSy[2] + sSy[3];
        float a  = sAcc[0] + sAcc[1] + sAcc[2] + sAcc[3];
        a += W4_F * loss_term(Sx, Sy, 1.0f / 16.0f);   // d=4 (16x16 tile)
        g_Sx[b] = Sx; g_Sy[b] = Sy; g_partial[b] = a;
        __threadfence();
        unsigned int t = atomicAdd(&g_count, 1u);
        isLast = (t == gridDim.x - 1);
    }
    __syncthreads();
    if (!isLast) return;

    // ---- Phase B: last CTA, 16x16 tile grid, levels d=3..0 ----
    __threadfence();
    {
        // Same geometry on the tile grid: warp w owns an 8x8 tile quadrant,
        // lane holds 2 horizontally-adjacent tiles.
        const int trow = (w >> 1) * 8 + (lane >> 2);
        const int tcol = (w & 1) * 8 + (lane & 3) * 2;
        const int ti   = trow * 16 + tcol;

        const float2 tx = *(const float2*)(g_Sx + ti);
        const float2 ty = *(const float2*)(g_Sy + ti);
        const float2 tp = *(const float2*)(g_partial + ti);

        float acc = tp.x + tp.y;                        // gather phase-A partials
        float s8x, s8y;
        warp_quadtree(tx.x + tx.y, ty.x + ty.y, acc, s8x, s8y,
                      W3_R, 1.0f / 32.0f, W2_R, 1.0f / 64.0f, W1_R, 1.0f / 128.0f);
        acc = warp_sum(acc);
        if (lane == 0) { sSx[w] = s8x; sSy[w] = s8y; sAcc[w] = acc; }
    }
    __syncthreads();

    if (tid == 0) {
        float Sx = sSx[0] + sSx[1] + sSx[2] + sSx[3];
        float Sy = sSy[0] + sSy[1] + sSy[2] + sSy[3];
        float a  = sAcc[0] + sAcc[1] + sAcc[2] + sAcc[3];
        a += W0_F * loss_term(Sx, Sy, 1.0f / 256.0f);   // d=0 (full image)
        out[0] = a;
        g_count = 0;                                    // reset for graph replay
    }
}

extern "C" void kernel_launch(void* const* d_in, const int* in_sizes, int n_in,
                              void* d_out, int out_size) {
    const float* x = (const float*)d_in[0];
    const float* y = (const float*)d_in[1];
    float* out = (float*)d_out;
    Loss_13967233646850_kernel<<<256, 128>>>(x, y, out);
}